// round 7
// baseline (speedup 1.0000x reference)
#include <cuda_runtime.h>
#include <cuda_fp16.h>
#include <cstdint>

// DAS beamforming: fp16 smem gather, TMA-bulk staged ring with per-buffer
// mbarrier full/empty pipeline (no block barriers in the main loop),
// packed f32x2 delay math + fp16 HFMA2 lerp.
// Pass 1: rf fp32 (8MB, L2-resident) -> fp16 __device__ buffer (4MB).
// Pass 2: block = (batch, 2048-pixel tile, 16-channel group); producer thread
// stages each channel's fp16 row (16KB) via cp.async.bulk into a 4-buffer
// ring; warps independently wait full[b], gather/lerp, arrive empty[b].

namespace {
constexpr int NB = 2;
constexpr int NC = 128;
constexpr int NS = 2048;
constexpr int M  = 65536;
constexpr int THREADS = 512;
constexpr int NWARPS = THREADS / 32;      // 16
constexpr int PXT = 4;                    // pixels per thread (2 packed pairs)
constexpr int TILE_P = THREADS * PXT;     // 2048
constexpr int TILES = M / TILE_P;         // 32
constexpr int CPG = 16;                   // channels per block
constexpr int NG  = NC / CPG;             // 8
constexpr int ROW_BYTES = NS * 8;         // fp16 row: 2048 samples * 8B = 16KB
constexpr int NBUF = 4;
constexpr int SMEM_BYTES = NBUF * ROW_BYTES;   // 64KB ring
constexpr int NSAMP = NB * NC * NS;
}

__device__ uint2 g_rf16[NSAMP];           // [B][Nc][Ns] x 4 halves = 4MB

// ---- packed f32x2 helpers ----
typedef unsigned long long ull;
__device__ __forceinline__ ull f2x_pack(float lo, float hi) {
    ull r; asm("mov.b64 %0, {%1, %2};" : "=l"(r) : "f"(lo), "f"(hi)); return r;
}
__device__ __forceinline__ void f2x_unpack(ull v, float& lo, float& hi) {
    asm("mov.b64 {%0, %1}, %2;" : "=f"(lo), "=f"(hi) : "l"(v));
}
__device__ __forceinline__ ull f2x_add(ull a, ull b) {
    ull r; asm("add.rn.f32x2 %0, %1, %2;" : "=l"(r) : "l"(a), "l"(b)); return r;
}
__device__ __forceinline__ ull f2x_mul(ull a, ull b) {
    ull r; asm("mul.rn.f32x2 %0, %1, %2;" : "=l"(r) : "l"(a), "l"(b)); return r;
}
__device__ __forceinline__ ull f2x_fma(ull a, ull b, ull c) {
    ull r; asm("fma.rn.f32x2 %0, %1, %2, %3;" : "=l"(r) : "l"(a), "l"(b), "l"(c));
    return r;
}

// ---- mbarrier / TMA bulk helpers ----
__device__ __forceinline__ void mbar_init(uint32_t a, uint32_t cnt) {
    asm volatile("mbarrier.init.shared.b64 [%0], %1;" :: "r"(a), "r"(cnt) : "memory");
}
__device__ __forceinline__ void mbar_arrive(uint32_t a) {
    asm volatile("mbarrier.arrive.shared.b64 _, [%0];" :: "r"(a) : "memory");
}
__device__ __forceinline__ void mbar_expect_tx(uint32_t a, uint32_t bytes) {
    asm volatile("mbarrier.arrive.expect_tx.shared.b64 _, [%0], %1;"
                 :: "r"(a), "r"(bytes) : "memory");
}
__device__ __forceinline__ void mbar_wait(uint32_t a, uint32_t parity) {
    asm volatile(
        "{\n\t"
        ".reg .pred P1;\n\t"
        "WAIT_LOOP_%=:\n\t"
        "mbarrier.try_wait.parity.acquire.cta.shared::cta.b64 P1, [%0], %1, 0x989680;\n\t"
        "@P1 bra.uni WAIT_DONE_%=;\n\t"
        "bra.uni WAIT_LOOP_%=;\n\t"
        "WAIT_DONE_%=:\n\t"
        "}"
        :: "r"(a), "r"(parity) : "memory");
}
__device__ __forceinline__ void tma_bulk_g2s(uint32_t dst, const void* src,
                                             uint32_t bytes, uint32_t mbar) {
    asm volatile(
        "cp.async.bulk.shared::cluster.global.mbarrier::complete_tx::bytes "
        "[%0], [%1], %2, [%3];"
        :: "r"(dst), "l"(src), "r"(bytes), "r"(mbar) : "memory");
}
__device__ __forceinline__ void red_add_v4(float* ptr, float x, float y, float z, float w) {
    asm volatile("red.global.add.v4.f32 [%0], {%1, %2, %3, %4};\n"
                 :: "l"(ptr), "f"(x), "f"(y), "f"(z), "f"(w) : "memory");
}

__global__ __launch_bounds__(256)
void rf_to_fp16_kernel(const float4* __restrict__ rf) {
    const int i = blockIdx.x * blockDim.x + threadIdx.x;
    if (i < NSAMP) {
        const float4 v = rf[i];
        const __half2 h0 = __float22half2_rn(make_float2(v.x, v.y));
        const __half2 h1 = __float22half2_rn(make_float2(v.z, v.w));
        uint2 u;
        u.x = *reinterpret_cast<const unsigned int*>(&h0);
        u.y = *reinterpret_cast<const unsigned int*>(&h1);
        g_rf16[i] = u;
    }
}

// Per-pixel: clamp delay, gather y0/y1, fp16 lerp, packed fp32 accumulate.
__device__ __forceinline__ void das_accum(float s, const uint2* __restrict__ cur,
                                          ull& acc_xy, ull& acc_zw) {
    s = fminf(fmaxf(s, 0.0f), (float)(NS - 1));   // fmaxf eats NaN (d2==0)
    int i0 = min((int)s, NS - 2);
    const float w = s - (float)i0;
    const __half2 wh = __float2half2_rn(w);

    const uint2 v0 = cur[i0];
    const uint2 v1 = cur[i0 + 1];
    const __half2 a0 = *reinterpret_cast<const __half2*>(&v0.x);
    const __half2 a1 = *reinterpret_cast<const __half2*>(&v0.y);
    const __half2 b0 = *reinterpret_cast<const __half2*>(&v1.x);
    const __half2 b1 = *reinterpret_cast<const __half2*>(&v1.y);

    const __half2 r0 = __hfma2(wh, __hsub2(b0, a0), a0);
    const __half2 r1 = __hfma2(wh, __hsub2(b1, a1), a1);

    const float2 f0 = __half22float2(r0);
    const float2 f1 = __half22float2(r1);
    acc_xy = f2x_add(acc_xy, f2x_pack(f0.x, f0.y));
    acc_zw = f2x_add(acc_zw, f2x_pack(f1.x, f1.y));
}

__global__ __launch_bounds__(THREADS, 3)
void das_fp16_kernel(const float* __restrict__ g,
                     const float* __restrict__ pr,
                     const float* __restrict__ p,
                     float* __restrict__ out) {
    extern __shared__ uint2 sbuf[];                 // [NBUF][NS]
    __shared__ __align__(8) unsigned long long mbar_full[NBUF];
    __shared__ __align__(8) unsigned long long mbar_empty[NBUF];
    __shared__ float sprx[CPG], spry[CPG], sprz[CPG];   // NEGATED positions

    const int tid  = threadIdx.x;
    int idx = blockIdx.x;
    const int b    = idx / (TILES * NG);
    idx -= b * (TILES * NG);
    const int tile = idx / NG;
    const int grp  = idx - tile * NG;
    const int c0   = grp * CPG;
    const int pm   = tile * TILE_P;

    const uint32_t full_a  = (uint32_t)__cvta_generic_to_shared(mbar_full);
    const uint32_t empty_a = (uint32_t)__cvta_generic_to_shared(mbar_empty);

    if (tid < CPG) {
        const float* prb = pr + ((size_t)b * NC + (c0 + tid)) * 3;
        sprx[tid] = -prb[0];
        spry[tid] = -prb[1];
        sprz[tid] = -prb[2];
    }
    if (tid < NBUF) {
        mbar_init(full_a + tid * 8, 1);          // expect_tx arrive
        mbar_init(empty_a + tid * 8, NWARPS);    // one arrive per warp
    }

    const float c0s = p[b * 4 + 0];
    const float fs  = p[b * 4 + 1];
    const float t0  = p[b * 4 + 2];
    const float scale = fs / c0s;
    const float tbase = fs * t0 / c0s;
    const ull scale2 = f2x_pack(scale, scale);
    const ull tbase2 = f2x_pack(tbase, tbase);

    ull gx2[PXT / 2], gy2[PXT / 2], gz2[PXT / 2];
    ull acc_xy[PXT], acc_zw[PXT];
    #pragma unroll
    for (int j2 = 0; j2 < PXT / 2; ++j2) {
        const int ma = pm + tid + (2 * j2 + 0) * THREADS;
        const int mb = pm + tid + (2 * j2 + 1) * THREADS;
        const float* ga = g + ((size_t)b * M + ma) * 3;
        const float* gb = g + ((size_t)b * M + mb) * 3;
        gx2[j2] = f2x_pack(ga[0], gb[0]);
        gy2[j2] = f2x_pack(ga[1], gb[1]);
        gz2[j2] = f2x_pack(ga[2], gb[2]);
    }
    #pragma unroll
    for (int j = 0; j < PXT; ++j) { acc_xy[j] = 0ULL; acc_zw[j] = 0ULL; }

    const uint2* rfb = g_rf16 + (size_t)b * NC * NS;
    const uint32_t sbase = (uint32_t)__cvta_generic_to_shared(sbuf);

    __syncthreads();   // mbarrier init + spr* visible to all

    // Producer: stage channel c into ring buffer (c & 3).
    auto stage = [&](int c) {
        const int bf = c & (NBUF - 1);
        const int fill = c >> 2;                 // reuse index of this buffer
        if (fill > 0) mbar_wait(empty_a + bf * 8, (fill - 1) & 1);
        mbar_expect_tx(full_a + bf * 8, ROW_BYTES);
        tma_bulk_g2s(sbase + bf * ROW_BYTES, rfb + (size_t)(c0 + c) * NS,
                     ROW_BYTES, full_a + bf * 8);
    };

    // Prologue: producer thread stages channels 0..2.
    if (tid == 0) { stage(0); stage(1); stage(2); }

    const int lane0 = ((tid & 31) == 0);

    for (int k = 0; k < CPG; ++k) {
        // Producer duties for channel k+3 (thread 0 only).
        if (tid == 0 && k + 3 < CPG) stage(k + 3);

        const int bf = k & (NBUF - 1);
        mbar_wait(full_a + bf * 8, (k >> 2) & 1);

        const uint2* cur = sbuf + (size_t)bf * NS;
        const ull nprx2 = f2x_pack(sprx[k], sprx[k]);
        const ull npry2 = f2x_pack(spry[k], spry[k]);
        const ull nprz2 = f2x_pack(sprz[k], sprz[k]);

        #pragma unroll
        for (int j2 = 0; j2 < PXT / 2; ++j2) {
            const ull dx2 = f2x_add(gx2[j2], nprx2);
            const ull dy2 = f2x_add(gy2[j2], npry2);
            const ull dz2 = f2x_add(gz2[j2], nprz2);
            ull d2 = f2x_mul(dz2, dz2);
            d2 = f2x_fma(dy2, dy2, d2);
            d2 = f2x_fma(dx2, dx2, d2);

            float d2a, d2b;
            f2x_unpack(d2, d2a, d2b);
            const ull r2 = f2x_pack(rsqrtf(d2a), rsqrtf(d2b));
            const ull drx2 = f2x_mul(d2, r2);          // sqrt(d2)
            const ull path2 = f2x_add(drx2, gz2[j2]);  // rx + tx(depth)
            const ull s2 = f2x_fma(scale2, path2, tbase2);

            float sa, sb;
            f2x_unpack(s2, sa, sb);
            das_accum(sa, cur, acc_xy[2 * j2 + 0], acc_zw[2 * j2 + 0]);
            das_accum(sb, cur, acc_xy[2 * j2 + 1], acc_zw[2 * j2 + 1]);
        }

        __syncwarp();
        if (lane0) mbar_arrive(empty_a + bf * 8);   // this warp done with bf
    }

    #pragma unroll
    for (int j = 0; j < PXT; ++j) {
        const int m = pm + tid + j * THREADS;
        float x, y, z, w;
        f2x_unpack(acc_xy[j], x, y);
        f2x_unpack(acc_zw[j], z, w);
        red_add_v4(out + ((size_t)b * M + m) * 4, x, y, z, w);
    }
}

extern "C" void kernel_launch(void* const* d_in, const int* in_sizes, int n_in,
                              void* d_out, int out_size) {
    const float* rf = (const float*)d_in[0];  // [B, Nc, Ns, K]
    const float* g  = (const float*)d_in[1];  // [B, Nz, Nx, 3]
    const float* pr = (const float*)d_in[2];  // [B, Nc, 3]
    const float* p  = (const float*)d_in[3];  // [B, 4]
    float* out = (float*)d_out;               // [B, Nz, Nx, K]

    cudaFuncSetAttribute(das_fp16_kernel,
                         cudaFuncAttributeMaxDynamicSharedMemorySize, SMEM_BYTES);

    rf_to_fp16_kernel<<<(NSAMP + 255) / 256, 256>>>(
        reinterpret_cast<const float4*>(rf));

    cudaMemsetAsync(out, 0, (size_t)out_size * sizeof(float));

    dim3 grid(NB * TILES * NG);   // 512 blocks
    das_fp16_kernel<<<grid, THREADS, SMEM_BYTES>>>(g, pr, p, out);
}

// round 8
// speedup vs baseline: 1.6305x; 1.6305x over previous
#include <cuda_runtime.h>
#include <cuda_fp16.h>
#include <cstdint>

// DAS beamforming: fp16-staged smem gather, 4-deep cp.async ring (syncthreads
// pipeline, R6 skeleton), packed f32x2 delay math + fp16 HFMA2 lerp,
// phase-split inner loop (delay calc -> batched LDS -> lerp/accum).
// Pass 1: rf fp32 (8MB, L2-resident) -> fp16 __device__ buffer (4MB).
// Pass 2: block = (batch, 2048-pixel tile, 16-channel group).

namespace {
constexpr int NB = 2;
constexpr int NC = 128;
constexpr int NS = 2048;
constexpr int M  = 65536;
constexpr int THREADS = 512;
constexpr int PXT = 4;                    // pixels per thread (2 packed pairs)
constexpr int TILE_P = THREADS * PXT;     // 2048
constexpr int TILES = M / TILE_P;         // 32
constexpr int CPG = 16;                   // channels per block
constexpr int NG  = NC / CPG;             // 8
constexpr int ROW_BYTES = NS * 8;         // fp16 row: 2048 samples * 8B
constexpr int NBUF = 4;
constexpr int SMEM_BYTES = NBUF * ROW_BYTES;   // 64KB ring
constexpr int NSAMP = NB * NC * NS;
}

__device__ uint2 g_rf16[NSAMP];           // [B][Nc][Ns] x 4 halves = 4MB

// ---- packed f32x2 helpers (ptxas never emits these from C++) ----
typedef unsigned long long ull;
__device__ __forceinline__ ull f2x_pack(float lo, float hi) {
    ull r; asm("mov.b64 %0, {%1, %2};" : "=l"(r) : "f"(lo), "f"(hi)); return r;
}
__device__ __forceinline__ void f2x_unpack(ull v, float& lo, float& hi) {
    asm("mov.b64 {%0, %1}, %2;" : "=f"(lo), "=f"(hi) : "l"(v));
}
__device__ __forceinline__ ull f2x_add(ull a, ull b) {
    ull r; asm("add.rn.f32x2 %0, %1, %2;" : "=l"(r) : "l"(a), "l"(b)); return r;
}
__device__ __forceinline__ ull f2x_mul(ull a, ull b) {
    ull r; asm("mul.rn.f32x2 %0, %1, %2;" : "=l"(r) : "l"(a), "l"(b)); return r;
}
__device__ __forceinline__ ull f2x_fma(ull a, ull b, ull c) {
    ull r; asm("fma.rn.f32x2 %0, %1, %2, %3;" : "=l"(r) : "l"(a), "l"(b), "l"(c));
    return r;
}

__device__ __forceinline__ void cp_async16(uint32_t smem_addr, const void* gptr) {
    asm volatile("cp.async.cg.shared.global [%0], [%1], 16;\n"
                 :: "r"(smem_addr), "l"(gptr) : "memory");
}
__device__ __forceinline__ void cp_async_commit() {
    asm volatile("cp.async.commit_group;\n" ::: "memory");
}
template <int N>
__device__ __forceinline__ void cp_async_wait() {
    asm volatile("cp.async.wait_group %0;\n" :: "n"(N) : "memory");
}
__device__ __forceinline__ void red_add_v4(float* ptr, float x, float y, float z, float w) {
    asm volatile("red.global.add.v4.f32 [%0], {%1, %2, %3, %4};\n"
                 :: "l"(ptr), "f"(x), "f"(y), "f"(z), "f"(w) : "memory");
}

__global__ __launch_bounds__(256)
void rf_to_fp16_kernel(const float4* __restrict__ rf) {
    const int i = blockIdx.x * blockDim.x + threadIdx.x;
    if (i < NSAMP) {
        const float4 v = rf[i];
        const __half2 h0 = __float22half2_rn(make_float2(v.x, v.y));
        const __half2 h1 = __float22half2_rn(make_float2(v.z, v.w));
        uint2 u;
        u.x = *reinterpret_cast<const unsigned int*>(&h0);
        u.y = *reinterpret_cast<const unsigned int*>(&h1);
        g_rf16[i] = u;
    }
}

__global__ __launch_bounds__(THREADS, 3)
void das_fp16_kernel(const float* __restrict__ g,
                     const float* __restrict__ pr,
                     const float* __restrict__ p,
                     float* __restrict__ out) {
    extern __shared__ uint2 sbuf[];                 // [NBUF][NS]
    __shared__ float sprx[CPG], spry[CPG], sprz[CPG];   // NEGATED positions

    const int tid  = threadIdx.x;
    int idx = blockIdx.x;
    const int b    = idx / (TILES * NG);
    idx -= b * (TILES * NG);
    const int tile = idx / NG;
    const int grp  = idx - tile * NG;
    const int c0   = grp * CPG;
    const int pm   = tile * TILE_P;

    if (tid < CPG) {
        const float* prb = pr + ((size_t)b * NC + (c0 + tid)) * 3;
        sprx[tid] = -prb[0];
        spry[tid] = -prb[1];
        sprz[tid] = -prb[2];
    }

    const float c0s = p[b * 4 + 0];
    const float fs  = p[b * 4 + 1];
    const float t0  = p[b * 4 + 2];
    const float scale = fs / c0s;
    const float tbase = fs * t0 / c0s;
    const ull scale2 = f2x_pack(scale, scale);
    const ull tbase2 = f2x_pack(tbase, tbase);

    // Packed per-pixel-pair coordinates, hoisted delay base, accumulators.
    ull gx2[PXT / 2], gy2[PXT / 2], gz2[PXT / 2], base2[PXT / 2];
    ull acc_xy[PXT], acc_zw[PXT];
    #pragma unroll
    for (int j2 = 0; j2 < PXT / 2; ++j2) {
        const int ma = pm + tid + (2 * j2 + 0) * THREADS;
        const int mb = pm + tid + (2 * j2 + 1) * THREADS;
        const float* ga = g + ((size_t)b * M + ma) * 3;
        const float* gb = g + ((size_t)b * M + mb) * 3;
        gx2[j2] = f2x_pack(ga[0], gb[0]);
        gy2[j2] = f2x_pack(ga[1], gb[1]);
        gz2[j2] = f2x_pack(ga[2], gb[2]);
        base2[j2] = f2x_fma(scale2, gz2[j2], tbase2);  // scale*gz + tbase
    }
    #pragma unroll
    for (int j = 0; j < PXT; ++j) { acc_xy[j] = 0ULL; acc_zw[j] = 0ULL; }

    const uint2* rfb = g_rf16 + (size_t)b * NC * NS;
    const uint32_t sbase = (uint32_t)__cvta_generic_to_shared(sbuf);

    auto stage = [&](int c, int buf) {
        const uint2* src = rfb + (size_t)c * NS;
        const uint32_t dst = sbase + (uint32_t)buf * ROW_BYTES;
        #pragma unroll
        for (int j = 0; j < NS / 2 / THREADS; ++j) {   // 2 iters of 16B chunks
            const int e = tid + j * THREADS;
            cp_async16(dst + e * 16, src + e * 2);
        }
    };

    stage(c0 + 0, 0); cp_async_commit();
    stage(c0 + 1, 1); cp_async_commit();
    stage(c0 + 2, 2); cp_async_commit();

    for (int k = 0; k < CPG; ++k) {
        __syncthreads();    // buffer (k+3)%4 free; k==0 also orders spr* writes

        if (k + 3 < CPG) stage(c0 + k + 3, (k + 3) & (NBUF - 1));
        cp_async_commit();          // exactly one group per iteration

        cp_async_wait<3>();         // groups g0..g_{k+3} committed -> g_k done

        const uint2* cur = sbuf + (size_t)(k & (NBUF - 1)) * NS;
        const ull nprx2 = f2x_pack(sprx[k], sprx[k]);
        const ull npry2 = f2x_pack(spry[k], spry[k]);
        const ull nprz2 = f2x_pack(sprz[k], sprz[k]);

        // Phase 1: delay values for all PXT pixels (packed pairs).
        float sv[PXT];
        #pragma unroll
        for (int j2 = 0; j2 < PXT / 2; ++j2) {
            const ull dx2 = f2x_add(gx2[j2], nprx2);
            const ull dy2 = f2x_add(gy2[j2], npry2);
            const ull dz2 = f2x_add(gz2[j2], nprz2);
            ull d2 = f2x_mul(dz2, dz2);
            d2 = f2x_fma(dy2, dy2, d2);
            d2 = f2x_fma(dx2, dx2, d2);

            float d2a, d2b;
            f2x_unpack(d2, d2a, d2b);
            const ull r2 = f2x_pack(rsqrtf(d2a), rsqrtf(d2b));
            const ull drx2 = f2x_mul(d2, r2);          // sqrt(d2)
            const ull s2 = f2x_fma(scale2, drx2, base2[j2]);
            f2x_unpack(s2, sv[2 * j2 + 0], sv[2 * j2 + 1]);
        }

        // Phase 2: clamp, index, and issue all 8 LDS back-to-back.
        float w[PXT];
        uint2 v0[PXT], v1[PXT];
        #pragma unroll
        for (int j = 0; j < PXT; ++j) {
            // upper clamp < 2047 so (int) gives i0 <= 2046 directly;
            // fmaxf eats NaN from d2==0.
            const float sc = fminf(fmaxf(sv[j], 0.0f), 2046.999f);
            const int i0 = (int)sc;
            w[j] = sc - (float)i0;
            v0[j] = cur[i0];
            v1[j] = cur[i0 + 1];
        }

        // Phase 3: fp16 lerp + packed fp32 accumulate.
        #pragma unroll
        for (int j = 0; j < PXT; ++j) {
            const __half2 wh = __float2half2_rn(w[j]);
            const __half2 a0 = *reinterpret_cast<const __half2*>(&v0[j].x);
            const __half2 a1 = *reinterpret_cast<const __half2*>(&v0[j].y);
            const __half2 b0 = *reinterpret_cast<const __half2*>(&v1[j].x);
            const __half2 b1 = *reinterpret_cast<const __half2*>(&v1[j].y);

            const __half2 r0 = __hfma2(wh, __hsub2(b0, a0), a0);
            const __half2 r1 = __hfma2(wh, __hsub2(b1, a1), a1);

            const float2 f0 = __half22float2(r0);
            const float2 f1 = __half22float2(r1);
            acc_xy[j] = f2x_add(acc_xy[j], f2x_pack(f0.x, f0.y));
            acc_zw[j] = f2x_add(acc_zw[j], f2x_pack(f1.x, f1.y));
        }
    }

    #pragma unroll
    for (int j = 0; j < PXT; ++j) {
        const int m = pm + tid + j * THREADS;
        float x, y, z, w;
        f2x_unpack(acc_xy[j], x, y);
        f2x_unpack(acc_zw[j], z, w);
        red_add_v4(out + ((size_t)b * M + m) * 4, x, y, z, w);
    }
}

extern "C" void kernel_launch(void* const* d_in, const int* in_sizes, int n_in,
                              void* d_out, int out_size) {
    const float* rf = (const float*)d_in[0];  // [B, Nc, Ns, K]
    const float* g  = (const float*)d_in[1];  // [B, Nz, Nx, 3]
    const float* pr = (const float*)d_in[2];  // [B, Nc, 3]
    const float* p  = (const float*)d_in[3];  // [B, 4]
    float* out = (float*)d_out;               // [B, Nz, Nx, K]

    cudaFuncSetAttribute(das_fp16_kernel,
                         cudaFuncAttributeMaxDynamicSharedMemorySize, SMEM_BYTES);

    rf_to_fp16_kernel<<<(NSAMP + 255) / 256, 256>>>(
        reinterpret_cast<const float4*>(rf));

    cudaMemsetAsync(out, 0, (size_t)out_size * sizeof(float));

    dim3 grid(NB * TILES * NG);   // 512 blocks
    das_fp16_kernel<<<grid, THREADS, SMEM_BYTES>>>(g, pr, p, out);
}

// round 10
// speedup vs baseline: 1.6996x; 1.0424x over previous
#include <cuda_runtime.h>
#include <cuda_fp16.h>
#include <cstdint>

// DAS beamforming: pair-duplicated fp16 smem gather (single LDS.128 fetches
// both interp rows), 3-deep cp.async ring with __syncthreads pipeline,
// packed f32x2 delay math + fp16 HFMA2 lerp.
// Pass 1: rf fp32 -> paired fp16 layout rfp[b][c][s] = {samples s, s+1} (8MB).
// Pass 2: block = (batch, 2048-pixel tile, 16-channel group).

namespace {
constexpr int NB = 2;
constexpr int NC = 128;
constexpr int NS = 2048;
constexpr int M  = 65536;
constexpr int THREADS = 512;
constexpr int PXT = 4;                    // pixels per thread (2 packed pairs)
constexpr int TILE_P = THREADS * PXT;     // 2048
constexpr int TILES = M / TILE_P;         // 32
constexpr int CPG = 16;                   // channels per block
constexpr int NG  = NC / CPG;             // 8
constexpr int ROW_BYTES = NS * 16;        // paired fp16 row: 32KB
constexpr int NBUF = 3;
constexpr int SMEM_BYTES = NBUF * ROW_BYTES;   // 96KB ring
constexpr int NSAMP = NB * NC * NS;
}

__device__ uint4 g_rfp[NSAMP];            // [B][Nc][Ns] paired-sample fp16, 8MB

// ---- packed f32x2 helpers (ptxas never emits these from C++) ----
typedef unsigned long long ull;
__device__ __forceinline__ ull f2x_pack(float lo, float hi) {
    ull r; asm("mov.b64 %0, {%1, %2};" : "=l"(r) : "f"(lo), "f"(hi)); return r;
}
__device__ __forceinline__ void f2x_unpack(ull v, float& lo, float& hi) {
    asm("mov.b64 {%0, %1}, %2;" : "=f"(lo), "=f"(hi) : "l"(v));
}
__device__ __forceinline__ ull f2x_add(ull a, ull b) {
    ull r; asm("add.rn.f32x2 %0, %1, %2;" : "=l"(r) : "l"(a), "l"(b)); return r;
}
__device__ __forceinline__ ull f2x_mul(ull a, ull b) {
    ull r; asm("mul.rn.f32x2 %0, %1, %2;" : "=l"(r) : "l"(a), "l"(b)); return r;
}
__device__ __forceinline__ ull f2x_fma(ull a, ull b, ull c) {
    ull r; asm("fma.rn.f32x2 %0, %1, %2, %3;" : "=l"(r) : "l"(a), "l"(b), "l"(c));
    return r;
}

__device__ __forceinline__ void cp_async16(uint32_t smem_addr, const void* gptr) {
    asm volatile("cp.async.cg.shared.global [%0], [%1], 16;\n"
                 :: "r"(smem_addr), "l"(gptr) : "memory");
}
__device__ __forceinline__ void cp_async_commit() {
    asm volatile("cp.async.commit_group;\n" ::: "memory");
}
template <int N>
__device__ __forceinline__ void cp_async_wait() {
    asm volatile("cp.async.wait_group %0;\n" :: "n"(N) : "memory");
}
__device__ __forceinline__ void red_add_v4(float* ptr, float x, float y, float z, float w) {
    asm volatile("red.global.add.v4.f32 [%0], {%1, %2, %3, %4};\n"
                 :: "l"(ptr), "f"(x), "f"(y), "f"(z), "f"(w) : "memory");
}

// Pass 1: build paired fp16 layout. Entry s holds fp16 of samples s and
// min(s+1, NS-1) of the same channel row.
__global__ __launch_bounds__(256)
void rf_pair_fp16_kernel(const float4* __restrict__ rf) {
    const int i = blockIdx.x * blockDim.x + threadIdx.x;
    if (i < NSAMP) {
        const int s = i & (NS - 1);
        const float4 v = rf[i];
        const float4 n = rf[(s < NS - 1) ? i + 1 : i];
        uint4 u;
        const __half2 h0 = __float22half2_rn(make_float2(v.x, v.y));
        const __half2 h1 = __float22half2_rn(make_float2(v.z, v.w));
        const __half2 h2 = __float22half2_rn(make_float2(n.x, n.y));
        const __half2 h3 = __float22half2_rn(make_float2(n.z, n.w));
        u.x = *reinterpret_cast<const unsigned int*>(&h0);
        u.y = *reinterpret_cast<const unsigned int*>(&h1);
        u.z = *reinterpret_cast<const unsigned int*>(&h2);
        u.w = *reinterpret_cast<const unsigned int*>(&h3);
        g_rfp[i] = u;
    }
}

__global__ __launch_bounds__(THREADS, 2)
void das_fp16_kernel(const float* __restrict__ g,
                     const float* __restrict__ pr,
                     const float* __restrict__ p,
                     float* __restrict__ out) {
    extern __shared__ uint4 sbuf[];                 // [NBUF][NS] 16B entries
    __shared__ float sprx[CPG], spry[CPG], sprz[CPG];   // NEGATED positions

    const int tid  = threadIdx.x;
    int idx = blockIdx.x;
    const int b    = idx / (TILES * NG);
    idx -= b * (TILES * NG);
    const int tile = idx / NG;
    const int grp  = idx - tile * NG;
    const int c0   = grp * CPG;
    const int pm   = tile * TILE_P;

    if (tid < CPG) {
        const float* prb = pr + ((size_t)b * NC + (c0 + tid)) * 3;
        sprx[tid] = -prb[0];
        spry[tid] = -prb[1];
        sprz[tid] = -prb[2];
    }

    const float c0s = p[b * 4 + 0];
    const float fs  = p[b * 4 + 1];
    const float t0  = p[b * 4 + 2];
    const float scale = fs / c0s;
    const float tbase = fs * t0 / c0s;
    const ull scale2 = f2x_pack(scale, scale);
    const ull tbase2 = f2x_pack(tbase, tbase);

    // Packed per-pixel-pair coordinates, hoisted delay base, accumulators.
    ull gx2[PXT / 2], gy2[PXT / 2], gz2[PXT / 2], base2[PXT / 2];
    ull acc_xy[PXT], acc_zw[PXT];
    #pragma unroll
    for (int j2 = 0; j2 < PXT / 2; ++j2) {
        const int ma = pm + tid + (2 * j2 + 0) * THREADS;
        const int mb = pm + tid + (2 * j2 + 1) * THREADS;
        const float* ga = g + ((size_t)b * M + ma) * 3;
        const float* gb = g + ((size_t)b * M + mb) * 3;
        gx2[j2] = f2x_pack(ga[0], gb[0]);
        gy2[j2] = f2x_pack(ga[1], gb[1]);
        gz2[j2] = f2x_pack(ga[2], gb[2]);
        base2[j2] = f2x_fma(scale2, gz2[j2], tbase2);  // scale*gz + tbase
    }
    #pragma unroll
    for (int j = 0; j < PXT; ++j) { acc_xy[j] = 0ULL; acc_zw[j] = 0ULL; }

    const uint4* rfb = g_rfp + (size_t)b * NC * NS;
    const uint32_t sbase = (uint32_t)__cvta_generic_to_shared(sbuf);

    // Stage one paired row (32KB) into ring buffer `buf`: 4 x 16B per thread.
    auto stage = [&](int c, int buf) {
        const uint4* src = rfb + (size_t)c * NS;
        const uint32_t dst = sbase + (uint32_t)buf * ROW_BYTES;
        #pragma unroll
        for (int j = 0; j < NS / THREADS; ++j) {       // 4 iters
            const int e = tid + j * THREADS;
            cp_async16(dst + e * 16, src + e);
        }
    };

    // Prologue: stage channels 0..1 as groups g0..g1.
    stage(c0 + 0, 0); cp_async_commit();
    stage(c0 + 1, 1); cp_async_commit();

    int buf = 2;    // ring position to stage next (k+2)
    for (int k = 0; k < CPG; ++k) {
        __syncthreads();    // consumers done with buffer being restaged;
                            // k==0 also orders the spr* smem writes

        if (k + 2 < CPG) stage(c0 + k + 2, buf);
        cp_async_commit();          // exactly one group per iteration

        cp_async_wait<2>();         // leave 2 newest in flight -> g_k complete

        const int cbuf = (buf + 1 < NBUF) ? buf + 1 : buf + 1 - NBUF; // == k%3
        if (++buf == NBUF) buf = 0;

        const uint4* cur = sbuf + (size_t)cbuf * NS;
        const ull nprx2 = f2x_pack(sprx[k], sprx[k]);
        const ull npry2 = f2x_pack(spry[k], spry[k]);
        const ull nprz2 = f2x_pack(sprz[k], sprz[k]);

        #pragma unroll
        for (int j2 = 0; j2 < PXT / 2; ++j2) {
            const ull dx2 = f2x_add(gx2[j2], nprx2);
            const ull dy2 = f2x_add(gy2[j2], npry2);
            const ull dz2 = f2x_add(gz2[j2], nprz2);
            ull d2 = f2x_mul(dz2, dz2);
            d2 = f2x_fma(dy2, dy2, d2);
            d2 = f2x_fma(dx2, dx2, d2);

            float d2a, d2b;
            f2x_unpack(d2, d2a, d2b);
            const ull r2 = f2x_pack(rsqrtf(d2a), rsqrtf(d2b));
            const ull drx2 = f2x_mul(d2, r2);          // sqrt(d2)
            const ull s2 = f2x_fma(scale2, drx2, base2[j2]);

            float sa, sb;
            f2x_unpack(s2, sa, sb);

            #pragma unroll
            for (int h = 0; h < 2; ++h) {
                const float sraw = h ? sb : sa;
                const int j = 2 * j2 + h;
                // clamp < 2047 so (int) gives i0 <= 2046; fmaxf eats NaN.
                const float sc = fminf(fmaxf(sraw, 0.0f), 2046.999f);
                const int i0 = (int)sc;
                const float w = sc - (float)i0;
                const __half2 wh = __float2half2_rn(w);

                const uint4 v = cur[i0];   // y0 (x,y) and y1 (z,w) together
                const __half2 a0 = *reinterpret_cast<const __half2*>(&v.x);
                const __half2 a1 = *reinterpret_cast<const __half2*>(&v.y);
                const __half2 b0 = *reinterpret_cast<const __half2*>(&v.z);
                const __half2 b1 = *reinterpret_cast<const __half2*>(&v.w);

                const __half2 r0 = __hfma2(wh, __hsub2(b0, a0), a0);
                const __half2 r1 = __hfma2(wh, __hsub2(b1, a1), a1);

                const float2 f0 = __half22float2(r0);
                const float2 f1 = __half22float2(r1);
                acc_xy[j] = f2x_add(acc_xy[j], f2x_pack(f0.x, f0.y));
                acc_zw[j] = f2x_add(acc_zw[j], f2x_pack(f1.x, f1.y));
            }
        }
    }

    #pragma unroll
    for (int j = 0; j < PXT; ++j) {
        const int m = pm + tid + j * THREADS;
        float x, y, z, w;
        f2x_unpack(acc_xy[j], x, y);
        f2x_unpack(acc_zw[j], z, w);
        red_add_v4(out + ((size_t)b * M + m) * 4, x, y, z, w);
    }
}

extern "C" void kernel_launch(void* const* d_in, const int* in_sizes, int n_in,
                              void* d_out, int out_size) {
    const float* rf = (const float*)d_in[0];  // [B, Nc, Ns, K]
    const float* g  = (const float*)d_in[1];  // [B, Nz, Nx, 3]
    const float* pr = (const float*)d_in[2];  // [B, Nc, 3]
    const float* p  = (const float*)d_in[3];  // [B, 4]
    float* out = (float*)d_out;               // [B, Nz, Nx, K]

    cudaFuncSetAttribute(das_fp16_kernel,
                         cudaFuncAttributeMaxDynamicSharedMemorySize, SMEM_BYTES);

    rf_pair_fp16_kernel<<<(NSAMP + 255) / 256, 256>>>(
        reinterpret_cast<const float4*>(rf));

    cudaMemsetAsync(out, 0, (size_t)out_size * sizeof(float));

    dim3 grid(NB * TILES * NG);   // 512 blocks
    das_fp16_kernel<<<grid, THREADS, SMEM_BYTES>>>(g, pr, p, out);
}

// round 11
// speedup vs baseline: 2.0432x; 1.2022x over previous
#include <cuda_runtime.h>
#include <cuda_fp16.h>
#include <cstdint>

// DAS beamforming: pair-duplicated fp16 smem gather (one LDS.128 fetches both
// interp rows), 3-deep ring staged by cp.async.bulk (TMA — zero LSU cycles),
// __syncthreads-per-channel pipeline + mbarrier completion, packed f32x2
// delay math + fp16 HFMA2 lerp.
// Pass 1: rf fp32 -> paired fp16 layout rfp[b][c][s] = {samples s, s+1} (8MB)
//         and zeroes the output (atomic accumulation target).
// Pass 2: block = (batch, 2048-pixel tile, 16-channel group).

namespace {
constexpr int NB = 2;
constexpr int NC = 128;
constexpr int NS = 2048;
constexpr int M  = 65536;
constexpr int THREADS = 512;
constexpr int PXT = 4;                    // pixels per thread (2 packed pairs)
constexpr int TILE_P = THREADS * PXT;     // 2048
constexpr int TILES = M / TILE_P;         // 32
constexpr int CPG = 16;                   // channels per block
constexpr int NG  = NC / CPG;             // 8
constexpr int ROW_BYTES = NS * 16;        // paired fp16 row: 32KB
constexpr int NBUF = 3;
constexpr int SMEM_BYTES = NBUF * ROW_BYTES;   // 96KB ring
constexpr int NSAMP = NB * NC * NS;       // 524288
constexpr int OUT_V4 = NB * M * 4 / 4;    // 131072 float4s in out
}

__device__ uint4 g_rfp[NSAMP];            // [B][Nc][Ns] paired-sample fp16, 8MB

// ---- packed f32x2 helpers (ptxas never emits these from C++) ----
typedef unsigned long long ull;
__device__ __forceinline__ ull f2x_pack(float lo, float hi) {
    ull r; asm("mov.b64 %0, {%1, %2};" : "=l"(r) : "f"(lo), "f"(hi)); return r;
}
__device__ __forceinline__ void f2x_unpack(ull v, float& lo, float& hi) {
    asm("mov.b64 {%0, %1}, %2;" : "=f"(lo), "=f"(hi) : "l"(v));
}
__device__ __forceinline__ ull f2x_add(ull a, ull b) {
    ull r; asm("add.rn.f32x2 %0, %1, %2;" : "=l"(r) : "l"(a), "l"(b)); return r;
}
__device__ __forceinline__ ull f2x_mul(ull a, ull b) {
    ull r; asm("mul.rn.f32x2 %0, %1, %2;" : "=l"(r) : "l"(a), "l"(b)); return r;
}
__device__ __forceinline__ ull f2x_fma(ull a, ull b, ull c) {
    ull r; asm("fma.rn.f32x2 %0, %1, %2, %3;" : "=l"(r) : "l"(a), "l"(b), "l"(c));
    return r;
}

// ---- TMA bulk + mbarrier helpers ----
__device__ __forceinline__ void mbar_init(uint32_t a, uint32_t cnt) {
    asm volatile("mbarrier.init.shared.b64 [%0], %1;" :: "r"(a), "r"(cnt) : "memory");
}
__device__ __forceinline__ void mbar_expect_tx(uint32_t a, uint32_t bytes) {
    asm volatile("mbarrier.arrive.expect_tx.shared.b64 _, [%0], %1;"
                 :: "r"(a), "r"(bytes) : "memory");
}
__device__ __forceinline__ void mbar_wait(uint32_t a, uint32_t parity) {
    asm volatile(
        "{\n\t"
        ".reg .pred P1;\n\t"
        "WAIT_LOOP_%=:\n\t"
        "mbarrier.try_wait.parity.acquire.cta.shared::cta.b64 P1, [%0], %1, 0x989680;\n\t"
        "@P1 bra.uni WAIT_DONE_%=;\n\t"
        "bra.uni WAIT_LOOP_%=;\n\t"
        "WAIT_DONE_%=:\n\t"
        "}"
        :: "r"(a), "r"(parity) : "memory");
}
__device__ __forceinline__ void tma_bulk_g2s(uint32_t dst, const void* src,
                                             uint32_t bytes, uint32_t mbar) {
    asm volatile(
        "cp.async.bulk.shared::cluster.global.mbarrier::complete_tx::bytes "
        "[%0], [%1], %2, [%3];"
        :: "r"(dst), "l"(src), "r"(bytes), "r"(mbar) : "memory");
}
__device__ __forceinline__ void red_add_v4(float* ptr, float x, float y, float z, float w) {
    asm volatile("red.global.add.v4.f32 [%0], {%1, %2, %3, %4};\n"
                 :: "l"(ptr), "f"(x), "f"(y), "f"(z), "f"(w) : "memory");
}

// Pass 1: build paired fp16 layout (entry s holds samples s and s+1 clamped)
// and zero the output buffer.
__global__ __launch_bounds__(256)
void rf_pair_fp16_kernel(const float4* __restrict__ rf, float4* __restrict__ out) {
    const int i = blockIdx.x * blockDim.x + threadIdx.x;
    if (i < NSAMP) {
        const int s = i & (NS - 1);
        const float4 v = rf[i];
        const float4 n = rf[(s < NS - 1) ? i + 1 : i];
        uint4 u;
        const __half2 h0 = __float22half2_rn(make_float2(v.x, v.y));
        const __half2 h1 = __float22half2_rn(make_float2(v.z, v.w));
        const __half2 h2 = __float22half2_rn(make_float2(n.x, n.y));
        const __half2 h3 = __float22half2_rn(make_float2(n.z, n.w));
        u.x = *reinterpret_cast<const unsigned int*>(&h0);
        u.y = *reinterpret_cast<const unsigned int*>(&h1);
        u.z = *reinterpret_cast<const unsigned int*>(&h2);
        u.w = *reinterpret_cast<const unsigned int*>(&h3);
        g_rfp[i] = u;
    }
    if (i < OUT_V4) {
        out[i] = make_float4(0.f, 0.f, 0.f, 0.f);
    }
}

__global__ __launch_bounds__(THREADS, 2)
void das_fp16_kernel(const float* __restrict__ g,
                     const float* __restrict__ pr,
                     const float* __restrict__ p,
                     float* __restrict__ out) {
    extern __shared__ uint4 sbuf[];                 // [NBUF][NS] 16B entries
    __shared__ __align__(8) unsigned long long mbar_full[NBUF];
    __shared__ float sprx[CPG], spry[CPG], sprz[CPG];   // NEGATED positions

    const int tid  = threadIdx.x;
    int idx = blockIdx.x;
    const int b    = idx / (TILES * NG);
    idx -= b * (TILES * NG);
    const int tile = idx / NG;
    const int grp  = idx - tile * NG;
    const int c0   = grp * CPG;
    const int pm   = tile * TILE_P;

    const uint32_t full_a = (uint32_t)__cvta_generic_to_shared(mbar_full);

    if (tid < CPG) {
        const float* prb = pr + ((size_t)b * NC + (c0 + tid)) * 3;
        sprx[tid] = -prb[0];
        spry[tid] = -prb[1];
        sprz[tid] = -prb[2];
    }
    if (tid < NBUF) {
        mbar_init(full_a + tid * 8, 1);   // one expect_tx arrive per fill
    }

    const float c0s = p[b * 4 + 0];
    const float fs  = p[b * 4 + 1];
    const float t0  = p[b * 4 + 2];
    const float scale = fs / c0s;
    const float tbase = fs * t0 / c0s;
    const ull scale2 = f2x_pack(scale, scale);
    const ull tbase2 = f2x_pack(tbase, tbase);

    // Packed per-pixel-pair coordinates, hoisted delay base, accumulators.
    ull gx2[PXT / 2], gy2[PXT / 2], gz2[PXT / 2], base2[PXT / 2];
    ull acc_xy[PXT], acc_zw[PXT];
    #pragma unroll
    for (int j2 = 0; j2 < PXT / 2; ++j2) {
        const int ma = pm + tid + (2 * j2 + 0) * THREADS;
        const int mb = pm + tid + (2 * j2 + 1) * THREADS;
        const float* ga = g + ((size_t)b * M + ma) * 3;
        const float* gb = g + ((size_t)b * M + mb) * 3;
        gx2[j2] = f2x_pack(ga[0], gb[0]);
        gy2[j2] = f2x_pack(ga[1], gb[1]);
        gz2[j2] = f2x_pack(ga[2], gb[2]);
        base2[j2] = f2x_fma(scale2, gz2[j2], tbase2);  // scale*gz + tbase
    }
    #pragma unroll
    for (int j = 0; j < PXT; ++j) { acc_xy[j] = 0ULL; acc_zw[j] = 0ULL; }

    const uint4* rfb = g_rfp + (size_t)b * NC * NS;
    const uint32_t sbase = (uint32_t)__cvta_generic_to_shared(sbuf);

    __syncthreads();   // mbarrier init visible before any expect_tx / wait

    // TMA-stage channel c into ring buffer bf (single thread, zero LSU work).
    auto stage = [&](int c, int bf) {
        mbar_expect_tx(full_a + bf * 8, ROW_BYTES);
        tma_bulk_g2s(sbase + (uint32_t)bf * ROW_BYTES,
                     rfb + (size_t)(c0 + c) * NS, ROW_BYTES, full_a + bf * 8);
    };

    // Prologue: stage channels 0,1 into buffers 0,1.
    if (tid == 0) { stage(0, 0); stage(1, 1); }

    int sb = 2;            // next ring slot to stage (channel k+2)
    int cbuf = 0, cph = 0; // consumer cursor: buffer k%3, phase (k/3)&1

    for (int k = 0; k < CPG; ++k) {
        // All warps finished consuming the buffer being restaged (it was
        // consumed in iteration k-1); also orders spr* writes at k==0.
        __syncthreads();

        if (tid == 0 && k + 2 < CPG) stage(k + 2, sb);
        if (++sb == NBUF) sb = 0;

        mbar_wait(full_a + cbuf * 8, cph);

        const uint4* cur = sbuf + (size_t)cbuf * NS;
        if (++cbuf == NBUF) { cbuf = 0; cph ^= 1; }

        const ull nprx2 = f2x_pack(sprx[k], sprx[k]);
        const ull npry2 = f2x_pack(spry[k], spry[k]);
        const ull nprz2 = f2x_pack(sprz[k], sprz[k]);

        #pragma unroll
        for (int j2 = 0; j2 < PXT / 2; ++j2) {
            const ull dx2 = f2x_add(gx2[j2], nprx2);
            const ull dy2 = f2x_add(gy2[j2], npry2);
            const ull dz2 = f2x_add(gz2[j2], nprz2);
            ull d2 = f2x_mul(dz2, dz2);
            d2 = f2x_fma(dy2, dy2, d2);
            d2 = f2x_fma(dx2, dx2, d2);

            float d2a, d2b;
            f2x_unpack(d2, d2a, d2b);
            const ull r2 = f2x_pack(rsqrtf(d2a), rsqrtf(d2b));
            const ull drx2 = f2x_mul(d2, r2);          // sqrt(d2)
            const ull s2 = f2x_fma(scale2, drx2, base2[j2]);

            float sa, sb2;
            f2x_unpack(s2, sa, sb2);

            #pragma unroll
            for (int h = 0; h < 2; ++h) {
                const float sraw = h ? sb2 : sa;
                const int j = 2 * j2 + h;
                // clamp < 2047 so (int) gives i0 <= 2046; fmaxf eats NaN.
                const float sc = fminf(fmaxf(sraw, 0.0f), 2046.999f);
                const int i0 = (int)sc;
                const float w = sc - (float)i0;
                const __half2 wh = __float2half2_rn(w);

                const uint4 v = cur[i0];   // y0 (x,y) and y1 (z,w) together
                const __half2 a0 = *reinterpret_cast<const __half2*>(&v.x);
                const __half2 a1 = *reinterpret_cast<const __half2*>(&v.y);
                const __half2 b0 = *reinterpret_cast<const __half2*>(&v.z);
                const __half2 b1 = *reinterpret_cast<const __half2*>(&v.w);

                const __half2 r0 = __hfma2(wh, __hsub2(b0, a0), a0);
                const __half2 r1 = __hfma2(wh, __hsub2(b1, a1), a1);

                const float2 f0 = __half22float2(r0);
                const float2 f1 = __half22float2(r1);
                acc_xy[j] = f2x_add(acc_xy[j], f2x_pack(f0.x, f0.y));
                acc_zw[j] = f2x_add(acc_zw[j], f2x_pack(f1.x, f1.y));
            }
        }
    }

    #pragma unroll
    for (int j = 0; j < PXT; ++j) {
        const int m = pm + tid + j * THREADS;
        float x, y, z, w;
        f2x_unpack(acc_xy[j], x, y);
        f2x_unpack(acc_zw[j], z, w);
        red_add_v4(out + ((size_t)b * M + m) * 4, x, y, z, w);
    }
}

extern "C" void kernel_launch(void* const* d_in, const int* in_sizes, int n_in,
                              void* d_out, int out_size) {
    const float* rf = (const float*)d_in[0];  // [B, Nc, Ns, K]
    const float* g  = (const float*)d_in[1];  // [B, Nz, Nx, 3]
    const float* pr = (const float*)d_in[2];  // [B, Nc, 3]
    const float* p  = (const float*)d_in[3];  // [B, 4]
    float* out = (float*)d_out;               // [B, Nz, Nx, K]

    cudaFuncSetAttribute(das_fp16_kernel,
                         cudaFuncAttributeMaxDynamicSharedMemorySize, SMEM_BYTES);

    // Pass 1: paired fp16 layout + zero out (atomic target).
    rf_pair_fp16_kernel<<<(NSAMP + 255) / 256, 256>>>(
        reinterpret_cast<const float4*>(rf), reinterpret_cast<float4*>(out));

    // Pass 2: beamform.
    dim3 grid(NB * TILES * NG);   // 512 blocks
    das_fp16_kernel<<<grid, THREADS, SMEM_BYTES>>>(g, pr, p, out);
}